// round 17
// baseline (speedup 1.0000x reference)
#include <cuda_runtime.h>
#include <cstdint>
#include <cuda_fp16.h>
#include <mma.h>

using namespace nvcuda;

// Problem constants
#define BB    32
#define NWIN  64
#define LL    49
#define DD    192
#define PROJ_ 256
#define HEADS 8
#define HD    32
#define MTOT  (BB * NWIN * LL)   // 100352

#define ALDH 40      // GEMM A smem stride in halves
#define QLDH 40      // attention q/k/v stride (halves)
#define SLDF 68      // attention score/staging stride (floats)
#define PLDH 136     // P stride in halves (= SLDF f32 reinterpreted)

// Scratch (device globals: allocation-free per harness rules)
__device__ __half g_Q[MTOT * PROJ_];
__device__ __half g_K[MTOT * PROJ_];
__device__ __half g_V[MTOT * PROJ_];
__device__ __half g_Wh[4 * DD * PROJ_];  // fp16-rounded weights (Wq|Wk|Wv|Ww)

// 0 = int32 mask, 1 = byte mask (bool/uint8), 2 = float32 mask
__device__ int g_mask_kind;

// ---------------------------------------------------------------------------
__global__ void detect_mask_kind(const unsigned int* __restrict__ m)
{
    const int lane = threadIdx.x;
    int not_int = 0, not_flt = 0;
    for (int i = lane; i < 256; i += 32) {
        unsigned int w = m[i];
        if (w > 1u) not_int = 1;
        if (w != 0u && w != 0x3F800000u) not_flt = 1;
    }
    not_int = __any_sync(0xffffffffu, not_int);
    not_flt = __any_sync(0xffffffffu, not_flt);
    if (lane == 0) {
        int kind;
        if (!not_int)      kind = 0;
        else if (!not_flt) kind = 2;
        else               kind = 1;
        g_mask_kind = kind;
    }
}

// ---------------------------------------------------------------------------
__global__ void round_all4(const float* __restrict__ s0, const float* __restrict__ s1,
                           const float* __restrict__ s2, const float* __restrict__ s3,
                           __half* __restrict__ dst, int n)
{
    const int i = blockIdx.x * 256 + threadIdx.x;
    if (i < 4 * n) {
        const int seg = i / n;
        const int off = i - seg * n;
        const float* s = (seg == 0) ? s0 : (seg == 1) ? s1 : (seg == 2) ? s2 : s3;
        dst[i] = __float2half_rn(s[off]);
    }
}

// ---------------------------------------------------------------------------
// cp.async helpers
// ---------------------------------------------------------------------------
__device__ __forceinline__ void cpa16(unsigned int saddr, const void* gptr)
{
    asm volatile("cp.async.ca.shared.global [%0], [%1], 16;\n" :: "r"(saddr), "l"(gptr));
}
__device__ __forceinline__ void cpa_commit()
{
    asm volatile("cp.async.commit_group;\n");
}
template <int N>
__device__ __forceinline__ void cpa_wait()
{
    asm volatile("cp.async.wait_group %0;\n" :: "n"(N));
}
__device__ __forceinline__ void named_bar(int id, int nthreads)
{
    asm volatile("bar.sync %0, %1;" :: "r"(id), "r"(nthreads) : "memory");
}

// ---------------------------------------------------------------------------
// Fused FP16 projection GEMMs (Q|K|V by blockIdx.z) — unchanged from R16.
// ---------------------------------------------------------------------------
__global__ __launch_bounds__(128, 3) void gemm_fp16_proj3(
    const float* __restrict__ A0, const float* __restrict__ A1,
    const float* __restrict__ A2,
    const __half* __restrict__ WhBase,
    const float* __restrict__ bq, const float* __restrict__ bk,
    __half* __restrict__ C0, __half* __restrict__ C1, __half* __restrict__ C2,
    int Nd, int Kd)
{
    constexpr int BN_ = 128;
    constexpr int BLDH = BN_ + 8;
    constexpr int FJ   = BN_ / 32;
    constexpr int ABUFH = 128 * ALDH;
    constexpr int BBUFH = 32 * BLDH;

    extern __shared__ char smraw[];
    float*  BiasR = (float*)smraw;
    __half* As    = (__half*)(smraw + BN_ * 4);
    __half* Bs    = As + 2 * ABUFH;
    float*  Cs    = (float*)(smraw + BN_ * 4);

    const int z = blockIdx.z;
    const float* A   = (z == 0) ? A0 : (z == 1) ? A1 : A2;
    const __half* Bh = WhBase + (size_t)z * DD * PROJ_;
    const float* bias = (z == 0) ? bq : (z == 1) ? bk : nullptr;
    __half* C = (z == 0) ? C0 : (z == 1) ? C1 : C2;

    const int tid = threadIdx.x;
    const int wid = tid >> 5;
    const int m0 = blockIdx.y * 128;
    const int n0 = blockIdx.x * BN_;

    const int lwr = (wid >> 1) * 64;
    const int lwc = (wid & 1) * 64;

    const int ar  = tid >> 3;
    const int ac4 = (tid & 7) << 2;
    constexpr int TPRB = BN_ / 8;
    constexpr int RPPB = 128 / TPRB;
    constexpr int NPB  = 32 / RPPB;
    const int br  = tid / TPRB;
    const int bc8 = (tid % TPRB) << 3;

    const unsigned int bs_base = (unsigned int)__cvta_generic_to_shared(Bs);

    for (int c = tid; c < BN_; c += 128) BiasR[c] = bias ? bias[n0 + c] : 0.0f;

    wmma::fragment<wmma::matrix_a, 16, 16, 16, __half, wmma::row_major> fa[4];
    wmma::fragment<wmma::matrix_b, 16, 16, 16, __half, wmma::row_major> fb;
    wmma::fragment<wmma::accumulator, 16, 16, 16, float> fc[4][FJ];

#pragma unroll
    for (int i = 0; i < 4; i++)
#pragma unroll
        for (int j = 0; j < FJ; j++)
            wmma::fill_fragment(fc[i][j], 0.0f);

    const int niter = Kd / 32;
    float4 areg[8];

    auto ldg_A = [&](int k0) {
#pragma unroll
        for (int p = 0; p < 8; p++) {
            const int row = ar + p * 16;
            areg[p] = *reinterpret_cast<const float4*>(
                &A[(size_t)(m0 + row) * Kd + k0 + ac4]);
        }
    };
    auto sts_A = [&](int buf) {
        __half* Ab = As + buf * ABUFH;
#pragma unroll
        for (int p = 0; p < 8; p++) {
            const int row = ar + p * 16;
            union { __half2 h[2]; uint2 u; } pk;
            pk.h[0] = __floats2half2_rn(areg[p].x, areg[p].y);
            pk.h[1] = __floats2half2_rn(areg[p].z, areg[p].w);
            *reinterpret_cast<uint2*>(&Ab[row * ALDH + ac4]) = pk.u;
        }
    };
    auto load_B = [&](int buf, int k0) {
        const unsigned int bsb = bs_base + (unsigned int)(buf * BBUFH) * 2u;
#pragma unroll
        for (int p = 0; p < NPB; p++) {
            const int row = br + p * RPPB;
            cpa16(bsb + (unsigned int)(row * BLDH + bc8) * 2u,
                  &Bh[(size_t)(k0 + row) * Nd + n0 + bc8]);
        }
        cpa_commit();
    };

    load_B(0, 0);
    ldg_A(0);
    sts_A(0);

    for (int it = 0; it < niter; it++) {
        const int buf = it & 1;
        if (it + 1 < niter) {
            ldg_A((it + 1) * 32);
            load_B(buf ^ 1, (it + 1) * 32);
            cpa_wait<1>();
        } else {
            cpa_wait<0>();
        }
        __syncthreads();

        const __half* Ab = As + buf * ABUFH;
        const __half* Bb = Bs + buf * BBUFH;

#pragma unroll
        for (int ks = 0; ks < 32; ks += 16) {
#pragma unroll
            for (int i = 0; i < 4; i++)
                wmma::load_matrix_sync(fa[i], &Ab[(lwr + i * 16) * ALDH + ks], ALDH);
#pragma unroll
            for (int j = 0; j < FJ; j++) {
                wmma::load_matrix_sync(fb, &Bb[ks * BLDH + lwc + j * 16], BLDH);
#pragma unroll
                for (int i = 0; i < 4; i++)
                    wmma::mma_sync(fc[i][j], fa[i], fb, fc[i][j]);
            }
        }

        if (it + 1 < niter) sts_A(buf ^ 1);
        __syncthreads();
    }

#pragma unroll
    for (int jh = 0; jh < 2; jh++) {
        if (lwc == jh * 64) {
#pragma unroll
            for (int j = 0; j < FJ; j++)
#pragma unroll
                for (int i = 0; i < 4; i++)
                    wmma::store_matrix_sync(
                        &Cs[(lwr + i * 16) * SLDF + j * 16],
                        fc[i][j], SLDF, wmma::mem_row_major);
        }
        __syncthreads();
        for (int idx = tid; idx < 128 * 16; idx += 128) {
            const int r  = idx >> 4;
            const int c4 = (idx & 15) << 2;
            const int cg = jh * 64 + c4;
            union { __half2 h[2]; uint2 u; } pk;
            pk.h[0] = __floats2half2_rn(Cs[r * SLDF + c4]     + BiasR[cg],
                                        Cs[r * SLDF + c4 + 1] + BiasR[cg + 1]);
            pk.h[1] = __floats2half2_rn(Cs[r * SLDF + c4 + 2] + BiasR[cg + 2],
                                        Cs[r * SLDF + c4 + 3] + BiasR[cg + 3]);
            *reinterpret_cast<uint2*>(&C[(size_t)(m0 + r) * Nd + n0 + cg]) = pk.u;
        }
        __syncthreads();
    }
}

// ---------------------------------------------------------------------------
// FP16 out GEMM (unchanged): C_f32[M,N] = Ah[M,K] @ Bh[K,N] + bias
// ---------------------------------------------------------------------------
__global__ __launch_bounds__(128) void gemm_fp16_out(
    const __half* __restrict__ Ah, const __half* __restrict__ Bh,
    const float* __restrict__ bias, float* __restrict__ C,
    int Nd, int Kd)
{
    constexpr int BN_ = 64;
    constexpr int BLDH = BN_ + 8;
    constexpr int FJ   = 2;
    constexpr int ABUFH = 128 * ALDH;
    constexpr int BBUFH = 32 * BLDH;

    extern __shared__ char smraw[];
    float*  BiasT = (float*)smraw;
    __half* As    = (__half*)(smraw + 16 * (BN_ + 4) * 4);
    __half* Bs    = As + 2 * ABUFH;

    const int tid = threadIdx.x;
    const int wid = tid >> 5;
    const int m0 = blockIdx.y * 128;
    const int n0 = blockIdx.x * BN_;

    const int lwr = (wid >> 1) * 64;
    const int lwc = (wid & 1) * 32;

    const int aro = tid >> 2;
    const int ac8 = (tid & 3) << 3;
    const int br  = tid >> 3;
    const int bc8 = (tid & 7) << 3;

    const unsigned int as_base = (unsigned int)__cvta_generic_to_shared(As);
    const unsigned int bs_base = (unsigned int)__cvta_generic_to_shared(Bs);

    for (int idx = tid; idx < 16 * BN_; idx += 128) {
        const int r = idx / BN_;
        const int c = idx - r * BN_;
        BiasT[r * (BN_ + 4) + c] = bias ? bias[n0 + c] : 0.0f;
    }

    wmma::fragment<wmma::matrix_a, 16, 16, 16, __half, wmma::row_major> fa[4];
    wmma::fragment<wmma::matrix_b, 16, 16, 16, __half, wmma::row_major> fb;
    wmma::fragment<wmma::accumulator, 16, 16, 16, float> fc[4][FJ];

#pragma unroll
    for (int i = 0; i < 4; i++)
#pragma unroll
        for (int j = 0; j < FJ; j++)
            wmma::fill_fragment(fc[i][j], 0.0f);

    const int niter = Kd / 32;

    auto load_stage = [&](int buf, int k0) {
        const unsigned int asb = as_base + (unsigned int)(buf * ABUFH) * 2u;
        const unsigned int bsb = bs_base + (unsigned int)(buf * BBUFH) * 2u;
#pragma unroll
        for (int p = 0; p < 4; p++) {
            const int row = aro + p * 32;
            cpa16(asb + (unsigned int)(row * ALDH + ac8) * 2u,
                  &Ah[(size_t)(m0 + row) * Kd + k0 + ac8]);
        }
#pragma unroll
        for (int p = 0; p < 2; p++) {
            const int row = br + p * 16;
            cpa16(bsb + (unsigned int)(row * BLDH + bc8) * 2u,
                  &Bh[(size_t)(k0 + row) * Nd + n0 + bc8]);
        }
        cpa_commit();
    };

    load_stage(0, 0);

    for (int it = 0; it < niter; it++) {
        const int buf = it & 1;
        if (it + 1 < niter) {
            load_stage(buf ^ 1, (it + 1) * 32);
            cpa_wait<1>();
        } else {
            cpa_wait<0>();
        }
        __syncthreads();

        const __half* Ab = As + buf * ABUFH;
        const __half* Bb = Bs + buf * BBUFH;

#pragma unroll
        for (int ks = 0; ks < 32; ks += 16) {
#pragma unroll
            for (int i = 0; i < 4; i++)
                wmma::load_matrix_sync(fa[i], &Ab[(lwr + i * 16) * ALDH + ks], ALDH);
#pragma unroll
            for (int j = 0; j < FJ; j++) {
                wmma::load_matrix_sync(fb, &Bb[ks * BLDH + lwc + j * 16], BLDH);
#pragma unroll
                for (int i = 0; i < 4; i++)
                    wmma::mma_sync(fc[i][j], fa[i], fb, fc[i][j]);
            }
        }
        __syncthreads();
    }

    wmma::fragment<wmma::accumulator, 16, 16, 16, float> fbias;
#pragma unroll
    for (int j = 0; j < FJ; j++) {
        wmma::load_matrix_sync(fbias, &BiasT[lwc + j * 16], BN_ + 4, wmma::mem_row_major);
#pragma unroll
        for (int i = 0; i < 4; i++) {
#pragma unroll
            for (int t = 0; t < fbias.num_elements; t++)
                fc[i][j].x[t] += fbias.x[t];
            wmma::store_matrix_sync(
                &C[(size_t)(m0 + lwr + i * 16) * Nd + n0 + lwc + j * 16],
                fc[i][j], Nd, wmma::mem_row_major);
        }
    }
}

// ---------------------------------------------------------------------------
// FP16 window attention, warp-pair synchronized:
// - warps (2t, 2t+1) own row tile t; all post-load deps stay inside the pair
// - 1 CTA barrier (after loads) + 3 named 64-thread barriers per pair
// - P written in place over ss rows (halves, stride PLDH=136)
// - output written warp-locally (no final CTA barrier)
// smem: [0,5120) qs | [5120,10240) ks | [10240,15360) vs | [15360,32768) ss/P
// ---------------------------------------------------------------------------
__global__ __launch_bounds__(256) void attn_fp16(
    const __half* __restrict__ Q, const __half* __restrict__ K,
    const __half* __restrict__ V, const void* __restrict__ mask,
    __half* __restrict__ O)
{
    __shared__ __align__(16) char sm[32768];
    __half* qs  = (__half*)(sm);
    __half* ks_ = (__half*)(sm + 5120);
    __half* vs  = (__half*)(sm + 10240);
    float*  ss  = (float*)(sm + 15360);
    __half* Ph  = (__half*)(sm + 15360);   // in-place P (halves, stride PLDH)

    const int bx = blockIdx.x;
    const int h  = bx & 7;
    const int nw = (bx >> 3) & 63;
    const int b  = bx >> 9;
    const size_t base = ((size_t)(b * NWIN + nw) * LL) * PROJ_ + h * HD;
    const int tid = threadIdx.x;
    const int w   = tid >> 5;
    const int lane = tid & 31;
    const int pair = w >> 1;         // 0..3 (row tile)
    const int u    = w & 1;          // 0..1 (col half within pair)
    const int mkind = g_mask_kind;

    // Zero ONLY vs pad rows (V pad must be finite-zero: P pad cols are exact 0,
    // but 0 * NaN would poison valid rows). q/k pad garbage flows only into
    // never-read ss regions / discarded output rows.
    {
        const __half hz = __float2half_rn(0.0f);
        for (int idx = tid; idx < 15 * QLDH; idx += 256) vs[49 * QLDH + idx] = hz;
    }
    for (int idx = tid; idx < LL * 8; idx += 256) {
        const int r = idx >> 3;
        const int c = (idx & 7) << 2;
        const size_t g = base + (size_t)r * PROJ_ + c;
        *reinterpret_cast<uint2*>(&qs[r * QLDH + c])  = *reinterpret_cast<const uint2*>(&Q[g]);
        *reinterpret_cast<uint2*>(&ks_[r * QLDH + c]) = *reinterpret_cast<const uint2*>(&K[g]);
        *reinterpret_cast<uint2*>(&vs[r * QLDH + c])  = *reinterpret_cast<const uint2*>(&V[g]);
    }

    // Prefetch mask bits for softmax rows r = pair*16 + u*8 + ri (ri 0..7)
    unsigned int mbits = 0;
    {
        const size_t moff = (size_t)nw * LL * LL;
        const int c1ok = (lane + 32 < LL);
#pragma unroll
        for (int ri = 0; ri < 8; ri++) {
            const int r = pair * 16 + u * 8 + ri;
            if (r < LL) {
                const size_t e0 = moff + (size_t)r * LL + lane;
                int m0, m1 = 0;
                if (mkind == 0) {
                    m0 = ((const int*)mask)[e0];
                    if (c1ok) m1 = ((const int*)mask)[e0 + 32];
                } else if (mkind == 1) {
                    m0 = ((const unsigned char*)mask)[e0];
                    if (c1ok) m1 = ((const unsigned char*)mask)[e0 + 32];
                } else {
                    m0 = (((const float*)mask)[e0] != 0.0f);
                    if (c1ok) m1 = (((const float*)mask)[e0 + 32] != 0.0f);
                }
                mbits |= (m0 ? 1u : 0u) << (2 * ri);
                mbits |= (m1 ? 1u : 0u) << (2 * ri + 1);
            }
        }
    }
    __syncthreads();   // the ONLY CTA-wide barrier

    // ---- S = Q @ K^T: warp computes tiles (pair, 2u) and (pair, 2u+1) ----
    {
        wmma::fragment<wmma::matrix_a, 16, 16, 16, __half, wmma::row_major> fa;
        wmma::fragment<wmma::matrix_b, 16, 16, 16, __half, wmma::col_major> fb;
        wmma::fragment<wmma::accumulator, 16, 16, 16, float> fc[2];
        wmma::fill_fragment(fc[0], 0.0f);
        wmma::fill_fragment(fc[1], 0.0f);

        const int tj0 = u * 2;
#pragma unroll
        for (int k = 0; k < 32; k += 16) {
            wmma::load_matrix_sync(fa, &qs[pair * 16 * QLDH + k], QLDH);
#pragma unroll
            for (int t = 0; t < 2; t++) {
                wmma::load_matrix_sync(fb, &ks_[(tj0 + t) * 16 * QLDH + k], QLDH);
                wmma::mma_sync(fc[t], fa, fb, fc[t]);
            }
        }
#pragma unroll
        for (int t = 0; t < 2; t++)
            wmma::store_matrix_sync(&ss[pair * 16 * SLDF + (tj0 + t) * 16], fc[t],
                                    SLDF, wmma::mem_row_major);
    }
    named_bar(1 + pair, 64);

    // ---- Fused scale + mask + max-free softmax, P written IN PLACE ----
    // Per warp: 8 rows (pair*16 + u*8 + ri). All lanes load v0/v1 before the
    // half stores (converged warp -> load-before-store order holds).
    {
        const float scale = 0.17677669529663687f;
        const int c1ok = (lane + 32 < LL);
#pragma unroll
        for (int ri = 0; ri < 8; ri++) {
            const int r = pair * 16 + u * 8 + ri;
            if (r < LL) {
                float v0 = ss[r * SLDF + lane] * scale;
                if ((mbits >> (2 * ri)) & 1u) v0 = -1000.0f;
                const float e0 = __expf(v0);
                float e1 = 0.0f;
                if (c1ok) {
                    float v1 = ss[r * SLDF + lane + 32] * scale;
                    if ((mbits >> (2 * ri + 1)) & 1u) v1 = -1000.0f;
                    e1 = __expf(v1);
                }
                float s = e0 + e1;
#pragma unroll
                for (int o = 16; o; o >>= 1) s += __shfl_xor_sync(0xffffffffu, s, o);
                const float inv = 1.0f / (s + 1e-30f);
                Ph[r * PLDH + lane] = __float2half_rn(e0 * inv);
                Ph[r * PLDH + 32 + lane] =
                    c1ok ? __float2half_rn(e1 * inv) : __float2half_rn(0.0f);
            }
        }
    }
    named_bar(1 + pair, 64);

    // ---- Out = P @ V: warp computes output tile (pair, u) ----
    wmma::fragment<wmma::accumulator, 16, 16, 16, float> fo;
    {
        wmma::fragment<wmma::matrix_a, 16, 16, 16, __half, wmma::row_major> pa;
        wmma::fragment<wmma::matrix_b, 16, 16, 16, __half, wmma::row_major> pb;
        wmma::fill_fragment(fo, 0.0f);
#pragma unroll
        for (int k = 0; k < 64; k += 16) {
            wmma::load_matrix_sync(pa, &Ph[pair * 16 * PLDH + k], PLDH);
            wmma::load_matrix_sync(pb, &vs[k * QLDH + u * 16], QLDH);
            wmma::mma_sync(fo, pa, pb, fo);
        }
    }
    // fo store overwrites P data of this pair's rows -> wait for partner's pa loads
    named_bar(1 + pair, 64);
    wmma::store_matrix_sync(&ss[pair * 16 * SLDF + u * 16], fo, SLDF,
                            wmma::mem_row_major);
    __syncwarp();

    // ---- Warp-local output write: own 16x16 tile (2 lanes per row) ----
    {
        const int rr = lane >> 1;
        const int c0 = (lane & 1) * 8;
        const int row = pair * 16 + rr;
        if (row < LL) {
            const float* src = &ss[row * SLDF + u * 16 + c0];
            union { __half2 h[4]; uint4 v; } pk;
            pk.h[0] = __floats2half2_rn(src[0], src[1]);
            pk.h[1] = __floats2half2_rn(src[2], src[3]);
            pk.h[2] = __floats2half2_rn(src[4], src[5]);
            pk.h[3] = __floats2half2_rn(src[6], src[7]);
            *reinterpret_cast<uint4*>(&O[base + (size_t)row * PROJ_ + u * 16 + c0]) = pk.v;
        }
    }
}

// ---------------------------------------------------------------------------
extern "C" void kernel_launch(void* const* d_in, const int* in_sizes, int n_in,
                              void* d_out, int out_size)
{
    const float* query = (const float*)d_in[0];
    const float* key_  = (const float*)d_in[1];
    const float* value = (const float*)d_in[2];
    const void*  mask  = d_in[3];
    const float* Wq = (const float*)d_in[4];
    const float* bq = (const float*)d_in[5];
    const float* Wk = (const float*)d_in[6];
    const float* bk = (const float*)d_in[7];
    const float* Wv = (const float*)d_in[8];
    const float* Ww = (const float*)d_in[9];
    const float* bw = (const float*)d_in[10];

    __half *qp, *kp, *vp, *wh;
    cudaGetSymbolAddress((void**)&qp, g_Q);
    cudaGetSymbolAddress((void**)&kp, g_K);
    cudaGetSymbolAddress((void**)&vp, g_V);
    cudaGetSymbolAddress((void**)&wh, g_Wh);

    __half* Wwh = wh + 3 * DD * PROJ_;

    const int smemProj = 128 * 4 + (2 * 128 * ALDH + 2 * 32 * (128 + 8)) * 2;
    const int smemOut  = 16 * (64 + 4) * 4 + (2 * 128 * ALDH + 2 * 32 * (64 + 8)) * 2;
    cudaFuncSetAttribute(gemm_fp16_proj3,
                         cudaFuncAttributeMaxDynamicSharedMemorySize, smemProj);
    cudaFuncSetAttribute(gemm_fp16_out,
                         cudaFuncAttributeMaxDynamicSharedMemorySize, smemOut);

    detect_mask_kind<<<1, 32>>>((const unsigned int*)mask);

    const int nel = DD * PROJ_;  // 49152
    round_all4<<<(4 * nel + 255) / 256, 256>>>(Wq, Wk, Wv, Ww, wh, nel);

    dim3 gproj(PROJ_ / 128, MTOT / 128, 3);   // (2, 784, 3)
    gemm_fp16_proj3<<<gproj, 128, smemProj>>>(query, key_, value, wh, bq, bk,
                                              qp, kp, vp, PROJ_, DD);

    attn_fp16<<<BB * NWIN * HEADS, 256>>>(qp, kp, vp, mask, qp);

    dim3 gout(DD / 64, MTOT / 128);        // (3, 784)
    gemm_fp16_out<<<gout, 128, smemOut>>>(qp, Wwh, bw, (float*)d_out, DD, PROJ_);
}